// round 1
// baseline (speedup 1.0000x reference)
#include <cuda_runtime.h>

// Problem constants (fixed shapes per reference: N=32, H=1024, W=1024 fp32).
#define Wd 1024
#define Hd 1024
#define Nd 32
#define H_TILE 32   // output rows per block; vertical read amplification = 36/32

// Composite filter: the reference applies the 2x2 stencil S (weights
// [[1,.5],[.5,.25]], forward taps, zero pad) four times, with batch
// reversals that cancel. S = [1,0.5] (x) [1,0.5] is separable, so
// S^4 = 1D taps (1+0.5z)^4 = [1, 2, 1.5, 0.5, 0.0625] along H and W.

__device__ __forceinline__ void load_hfilter(const float* __restrict__ img,
                                             int r, int j, bool hasB,
                                             float hh[4]) {
    float a0,a1,a2,a3,a4,a5,a6,a7;
    if (r < Hd) {
        const float4 A = *reinterpret_cast<const float4*>(img + (size_t)r * Wd + j);
        a0 = A.x; a1 = A.y; a2 = A.z; a3 = A.w;
        if (hasB) {
            const float4 B = *reinterpret_cast<const float4*>(img + (size_t)r * Wd + j + 4);
            a4 = B.x; a5 = B.y; a6 = B.z; a7 = B.w;
        } else {
            a4 = a5 = a6 = a7 = 0.0f;   // zero pad beyond W (only j==W-4 thread)
        }
    } else {
        a0=a1=a2=a3=a4=a5=a6=a7 = 0.0f; // zero pad beyond H
    }
    // 5-tap horizontal: h[t] = a[t] + 2a[t+1] + 1.5a[t+2] + 0.5a[t+3] + 0.0625a[t+4]
    float v;
    v = fmaf(2.0f, a1, a0); v = fmaf(1.5f, a2, v); v = fmaf(0.5f, a3, v); hh[0] = fmaf(0.0625f, a4, v);
    v = fmaf(2.0f, a2, a1); v = fmaf(1.5f, a3, v); v = fmaf(0.5f, a4, v); hh[1] = fmaf(0.0625f, a5, v);
    v = fmaf(2.0f, a3, a2); v = fmaf(1.5f, a4, v); v = fmaf(0.5f, a5, v); hh[2] = fmaf(0.0625f, a6, v);
    v = fmaf(2.0f, a4, a3); v = fmaf(1.5f, a5, v); v = fmaf(0.5f, a6, v); hh[3] = fmaf(0.0625f, a7, v);
}

__global__ __launch_bounds__(256, 4)
void stencil4_kernel(const float* __restrict__ in, float* __restrict__ out) {
    const int tx = threadIdx.x;           // 0..255
    const int j  = tx << 2;               // column of this thread's float4
    const int row0 = blockIdx.x * H_TILE; // first output row of this block
    const size_t imgOff = (size_t)blockIdx.y * (size_t)Hd * Wd;
    const float* __restrict__ img = in + imgOff;
    float* __restrict__ o = out + imgOff;
    const bool hasB = (j + 4) < Wd;

    // Ring buffer of horizontally-filtered rows (5 rows x 4 cols in registers)
    float h[5][4];

    #pragma unroll
    for (int k = 0; k < 4; k++)
        load_hfilter(img, row0 + k, j, hasB, h[k]);

    #pragma unroll
    for (int rr = 0; rr < H_TILE; rr++) {
        load_hfilter(img, row0 + rr + 4, j, hasB, h[(rr + 4) % 5]);

        const int s0 = rr % 5, s1 = (rr + 1) % 5, s2 = (rr + 2) % 5,
                  s3 = (rr + 3) % 5, s4 = (rr + 4) % 5;
        float4 R;
        {
            float v;
            v = fmaf(2.0f, h[s1][0], h[s0][0]); v = fmaf(1.5f, h[s2][0], v);
            v = fmaf(0.5f, h[s3][0], v);        R.x = fmaf(0.0625f, h[s4][0], v);
            v = fmaf(2.0f, h[s1][1], h[s0][1]); v = fmaf(1.5f, h[s2][1], v);
            v = fmaf(0.5f, h[s3][1], v);        R.y = fmaf(0.0625f, h[s4][1], v);
            v = fmaf(2.0f, h[s1][2], h[s0][2]); v = fmaf(1.5f, h[s2][2], v);
            v = fmaf(0.5f, h[s3][2], v);        R.z = fmaf(0.0625f, h[s4][2], v);
            v = fmaf(2.0f, h[s1][3], h[s0][3]); v = fmaf(1.5f, h[s2][3], v);
            v = fmaf(0.5f, h[s3][3], v);        R.w = fmaf(0.0625f, h[s4][3], v);
        }
        *reinterpret_cast<float4*>(o + (size_t)(row0 + rr) * Wd + j) = R;
    }
}

extern "C" void kernel_launch(void* const* d_in, const int* in_sizes, int n_in,
                              void* d_out, int out_size) {
    const float* img = (const float*)d_in[0];
    float* out = (float*)d_out;
    dim3 grid(Hd / H_TILE, Nd);   // 32 x 32 = 1024 CTAs
    dim3 block(256);
    stencil4_kernel<<<grid, block>>>(img, out);
}

// round 2
// speedup vs baseline: 1.0747x; 1.0747x over previous
#include <cuda_runtime.h>

// Problem constants (fixed shapes per reference: N=32, H=1024, W=1024 fp32).
#define Wd 1024
#define Hd 1024
#define Nd 32
#define H_TILE 16   // output rows per block; vertical read amplification = 20/16

// Composite filter: the reference applies the 2x2 stencil S (weights
// [[1,.5],[.5,.25]], forward taps, zero pad) four times, with batch
// reversals that cancel. S = [1,0.5] (x) [1,0.5] is separable, so
// S^4 = 1D taps (1+0.5z)^4 = [1, 2, 1.5, 0.5, 0.0625] along H and W.

__device__ __forceinline__ void load_hfilter(const float* __restrict__ img,
                                             int r, int j, bool hasB,
                                             float hh[4]) {
    float a0,a1,a2,a3,a4,a5,a6,a7;
    if (r < Hd) {
        const float4 A = *reinterpret_cast<const float4*>(img + (size_t)r * Wd + j);
        a0 = A.x; a1 = A.y; a2 = A.z; a3 = A.w;
        if (hasB) {
            const float4 B = *reinterpret_cast<const float4*>(img + (size_t)r * Wd + j + 4);
            a4 = B.x; a5 = B.y; a6 = B.z; a7 = B.w;
        } else {
            a4 = a5 = a6 = a7 = 0.0f;   // zero pad beyond W (only j==W-4 thread)
        }
    } else {
        a0=a1=a2=a3=a4=a5=a6=a7 = 0.0f; // zero pad beyond H
    }
    // 5-tap horizontal: h[t] = a[t] + 2a[t+1] + 1.5a[t+2] + 0.5a[t+3] + 0.0625a[t+4]
    float v;
    v = fmaf(2.0f, a1, a0); v = fmaf(1.5f, a2, v); v = fmaf(0.5f, a3, v); hh[0] = fmaf(0.0625f, a4, v);
    v = fmaf(2.0f, a2, a1); v = fmaf(1.5f, a3, v); v = fmaf(0.5f, a4, v); hh[1] = fmaf(0.0625f, a5, v);
    v = fmaf(2.0f, a3, a2); v = fmaf(1.5f, a4, v); v = fmaf(0.5f, a5, v); hh[2] = fmaf(0.0625f, a6, v);
    v = fmaf(2.0f, a4, a3); v = fmaf(1.5f, a5, v); v = fmaf(0.5f, a6, v); hh[3] = fmaf(0.0625f, a7, v);
}

__global__ __launch_bounds__(256, 6)
void stencil4_kernel(const float* __restrict__ in, float* __restrict__ out) {
    const int tx = threadIdx.x;           // 0..255
    const int j  = tx << 2;               // column of this thread's float4
    const int row0 = blockIdx.x * H_TILE; // first output row of this block
    const size_t imgOff = (size_t)blockIdx.y * (size_t)Hd * Wd;
    const float* __restrict__ img = in + imgOff;
    float* __restrict__ o = out + imgOff;
    const bool hasB = (j + 4) < Wd;

    // Ring buffer of horizontally-filtered rows (5 rows x 4 cols in registers)
    float h[5][4];

    #pragma unroll
    for (int k = 0; k < 4; k++)
        load_hfilter(img, row0 + k, j, hasB, h[k]);

    #pragma unroll
    for (int rr = 0; rr < H_TILE; rr++) {
        load_hfilter(img, row0 + rr + 4, j, hasB, h[(rr + 4) % 5]);

        const int s0 = rr % 5, s1 = (rr + 1) % 5, s2 = (rr + 2) % 5,
                  s3 = (rr + 3) % 5, s4 = (rr + 4) % 5;
        float4 R;
        {
            float v;
            v = fmaf(2.0f, h[s1][0], h[s0][0]); v = fmaf(1.5f, h[s2][0], v);
            v = fmaf(0.5f, h[s3][0], v);        R.x = fmaf(0.0625f, h[s4][0], v);
            v = fmaf(2.0f, h[s1][1], h[s0][1]); v = fmaf(1.5f, h[s2][1], v);
            v = fmaf(0.5f, h[s3][1], v);        R.y = fmaf(0.0625f, h[s4][1], v);
            v = fmaf(2.0f, h[s1][2], h[s0][2]); v = fmaf(1.5f, h[s2][2], v);
            v = fmaf(0.5f, h[s3][2], v);        R.z = fmaf(0.0625f, h[s4][2], v);
            v = fmaf(2.0f, h[s1][3], h[s0][3]); v = fmaf(1.5f, h[s2][3], v);
            v = fmaf(0.5f, h[s3][3], v);        R.w = fmaf(0.0625f, h[s4][3], v);
        }
        *reinterpret_cast<float4*>(o + (size_t)(row0 + rr) * Wd + j) = R;
    }
}

extern "C" void kernel_launch(void* const* d_in, const int* in_sizes, int n_in,
                              void* d_out, int out_size) {
    const float* img = (const float*)d_in[0];
    float* out = (float*)d_out;
    dim3 grid(Hd / H_TILE, Nd);   // 64 x 32 = 2048 CTAs
    dim3 block(256);
    stencil4_kernel<<<grid, block>>>(img, out);
}

// round 3
// speedup vs baseline: 1.2988x; 1.2086x over previous
#include <cuda_runtime.h>

// Problem constants (fixed shapes per reference: N=32, H=1024, W=1024 fp32).
#define Wd 1024
#define Hd 1024
#define Nd 32
#define H_TILE 8            // output rows per block
#define H_IN   (H_TILE + 4) // input rows needed (5-tap forward filter)

// Composite filter: reference applies 2x2 stencil S (weights [[1,.5],[.5,.25]],
// forward taps, zero pad) 4 times; batch reversals cancel. S is separable, so
// S^4 = 1D taps (1+0.5z)^4 = [1, 2, 1.5, 0.5, 0.0625] along H and W.

__global__ __launch_bounds__(256, 2)
void stencil4_kernel(const float* __restrict__ in, float* __restrict__ out) {
    const int tx = threadIdx.x;           // 0..255
    const int j  = tx << 2;               // column of this thread's float4
    const int row0 = blockIdx.x * H_TILE; // first output row of this block
    const size_t imgOff = (size_t)blockIdx.y * (size_t)Hd * Wd;
    const float* __restrict__ img = in + imgOff;
    float* __restrict__ o = out + imgOff;
    const bool hasB = (j + 4) < Wd;

    // ---- Front-batch ALL loads: 12 rows x 2 float4, fully independent ----
    float4 A[H_IN], B[H_IN];
    #pragma unroll
    for (int r = 0; r < H_IN; r++) {
        const int gr = row0 + r;
        if (gr < Hd) {
            A[r] = *reinterpret_cast<const float4*>(img + (size_t)gr * Wd + j);
            if (hasB)
                B[r] = *reinterpret_cast<const float4*>(img + (size_t)gr * Wd + j + 4);
            else
                B[r] = make_float4(0.f, 0.f, 0.f, 0.f);
        } else {
            A[r] = make_float4(0.f, 0.f, 0.f, 0.f);
            B[r] = make_float4(0.f, 0.f, 0.f, 0.f);
        }
    }

    // ---- Horizontal 5-tap per row: h[t] = a[t] + 2a[t+1] + 1.5a[t+2] + 0.5a[t+3] + 0.0625a[t+4]
    float h[H_IN][4];
    #pragma unroll
    for (int r = 0; r < H_IN; r++) {
        const float a0 = A[r].x, a1 = A[r].y, a2 = A[r].z, a3 = A[r].w;
        const float a4 = B[r].x, a5 = B[r].y, a6 = B[r].z, a7 = B[r].w;
        float v;
        v = fmaf(2.0f, a1, a0); v = fmaf(1.5f, a2, v); v = fmaf(0.5f, a3, v); h[r][0] = fmaf(0.0625f, a4, v);
        v = fmaf(2.0f, a2, a1); v = fmaf(1.5f, a3, v); v = fmaf(0.5f, a4, v); h[r][1] = fmaf(0.0625f, a5, v);
        v = fmaf(2.0f, a3, a2); v = fmaf(1.5f, a4, v); v = fmaf(0.5f, a5, v); h[r][2] = fmaf(0.0625f, a6, v);
        v = fmaf(2.0f, a4, a3); v = fmaf(1.5f, a5, v); v = fmaf(0.5f, a6, v); h[r][3] = fmaf(0.0625f, a7, v);
    }

    // ---- Vertical 5-tap + streaming store ----
    #pragma unroll
    for (int rr = 0; rr < H_TILE; rr++) {
        float4 R;
        float v;
        v = fmaf(2.0f, h[rr+1][0], h[rr][0]); v = fmaf(1.5f, h[rr+2][0], v);
        v = fmaf(0.5f, h[rr+3][0], v);        R.x = fmaf(0.0625f, h[rr+4][0], v);
        v = fmaf(2.0f, h[rr+1][1], h[rr][1]); v = fmaf(1.5f, h[rr+2][1], v);
        v = fmaf(0.5f, h[rr+3][1], v);        R.y = fmaf(0.0625f, h[rr+4][1], v);
        v = fmaf(2.0f, h[rr+1][2], h[rr][2]); v = fmaf(1.5f, h[rr+2][2], v);
        v = fmaf(0.5f, h[rr+3][2], v);        R.z = fmaf(0.0625f, h[rr+4][2], v);
        v = fmaf(2.0f, h[rr+1][3], h[rr][3]); v = fmaf(1.5f, h[rr+2][3], v);
        v = fmaf(0.5f, h[rr+3][3], v);        R.w = fmaf(0.0625f, h[rr+4][3], v);
        __stcs(reinterpret_cast<float4*>(o + (size_t)(row0 + rr) * Wd + j), R);
    }
}

extern "C" void kernel_launch(void* const* d_in, const int* in_sizes, int n_in,
                              void* d_out, int out_size) {
    const float* img = (const float*)d_in[0];
    float* out = (float*)d_out;
    dim3 grid(Hd / H_TILE, Nd);   // 128 x 32 = 4096 CTAs
    dim3 block(256);
    stencil4_kernel<<<grid, block>>>(img, out);
}

// round 4
// speedup vs baseline: 1.3780x; 1.0610x over previous
#include <cuda_runtime.h>
#include <cstdint>

// N=32, H=1024, W=1024 fp32.
// Composite filter: reference applies 2x2 stencil S (forward taps
// [[1,.5],[.5,.25]], zero pad) 4x; batch reversals cancel; S separable, so
// S^4 = 1D taps (1+0.5z)^4 = [1, 2, 1.5, 0.5, 0.0625] along H and W.
#define Wd 1024
#define Hd 1024
#define Nd 32
#define H_TILE 8
#define H_IN   12                 // H_TILE + 4 halo rows
#define IN_STRIDE 1032            // floats per smem row (1024 + 4 halo + 4 pad)
#define CH_PER_ROW 257            // 16B chunks per row we fill (1028 floats)
#define TOTAL_CH (H_IN * CH_PER_ROW)   // 3084

__device__ __forceinline__ uint32_t smem_u32(const void* p) {
    uint32_t a;
    asm("{ .reg .u64 t; cvta.to.shared.u64 t, %1; cvt.u32.u64 %0, t; }" : "=r"(a) : "l"(p));
    return a;
}

__global__ __launch_bounds__(256)
void stencil4_kernel(const float* __restrict__ in, float* __restrict__ out) {
    extern __shared__ float s[];   // H_IN * IN_STRIDE floats = 49536 B
    const int tx = threadIdx.x;    // 0..255
    const int row0 = blockIdx.x * H_TILE;
    const size_t imgOff = (size_t)blockIdx.y * (size_t)Hd * Wd;
    const float* __restrict__ img = in + imgOff;
    float* __restrict__ o = out + imgOff;

    const uint32_t sbase = smem_u32(s);

    // ---- Async load: 12 rows x 1028 cols into smem (zero-fill OOB) ----
    #pragma unroll
    for (int k = 0; k < 13; k++) {
        const int idx = k * 256 + tx;
        if (idx < TOTAL_CH) {
            const int row   = idx / CH_PER_ROW;        // 0..11
            const int chunk = idx - row * CH_PER_ROW;  // 0..256
            const int gr = row0 + row;
            const int n = (gr < Hd && chunk < 256) ? 16 : 0;   // zfill OOB
            const float* src = img + (size_t)min(gr, Hd - 1) * Wd + min(chunk, 255) * 4;
            const uint32_t dst = sbase + (uint32_t)(row * IN_STRIDE + chunk * 4) * 4u;
            asm volatile("cp.async.cg.shared.global [%0], [%1], 16, %2;\n"
                         :: "r"(dst), "l"(src), "r"(n) : "memory");
        }
    }
    asm volatile("cp.async.commit_group;\n" ::: "memory");
    asm volatile("cp.async.wait_group 0;\n" ::: "memory");
    __syncthreads();

    // ---- Horizontal 5-tap per row from smem ----
    const int j = tx << 2;         // this thread's 4 output columns
    float h[H_IN][4];
    #pragma unroll
    for (int r = 0; r < H_IN; r++) {
        const float4 A = *reinterpret_cast<const float4*>(&s[r * IN_STRIDE + j]);
        const float4 B = *reinterpret_cast<const float4*>(&s[r * IN_STRIDE + j + 4]);
        const float a0 = A.x, a1 = A.y, a2 = A.z, a3 = A.w;
        const float a4 = B.x, a5 = B.y, a6 = B.z, a7 = B.w;
        float v;
        v = fmaf(2.0f, a1, a0); v = fmaf(1.5f, a2, v); v = fmaf(0.5f, a3, v); h[r][0] = fmaf(0.0625f, a4, v);
        v = fmaf(2.0f, a2, a1); v = fmaf(1.5f, a3, v); v = fmaf(0.5f, a4, v); h[r][1] = fmaf(0.0625f, a5, v);
        v = fmaf(2.0f, a3, a2); v = fmaf(1.5f, a4, v); v = fmaf(0.5f, a5, v); h[r][2] = fmaf(0.0625f, a6, v);
        v = fmaf(2.0f, a4, a3); v = fmaf(1.5f, a5, v); v = fmaf(0.5f, a6, v); h[r][3] = fmaf(0.0625f, a7, v);
    }

    // ---- Vertical 5-tap + streaming stores ----
    #pragma unroll
    for (int rr = 0; rr < H_TILE; rr++) {
        float4 R;
        float v;
        v = fmaf(2.0f, h[rr+1][0], h[rr][0]); v = fmaf(1.5f, h[rr+2][0], v);
        v = fmaf(0.5f, h[rr+3][0], v);        R.x = fmaf(0.0625f, h[rr+4][0], v);
        v = fmaf(2.0f, h[rr+1][1], h[rr][1]); v = fmaf(1.5f, h[rr+2][1], v);
        v = fmaf(0.5f, h[rr+3][1], v);        R.y = fmaf(0.0625f, h[rr+4][1], v);
        v = fmaf(2.0f, h[rr+1][2], h[rr][2]); v = fmaf(1.5f, h[rr+2][2], v);
        v = fmaf(0.5f, h[rr+3][2], v);        R.z = fmaf(0.0625f, h[rr+4][2], v);
        v = fmaf(2.0f, h[rr+1][3], h[rr][3]); v = fmaf(1.5f, h[rr+2][3], v);
        v = fmaf(0.5f, h[rr+3][3], v);        R.w = fmaf(0.0625f, h[rr+4][3], v);
        __stcs(reinterpret_cast<float4*>(o + (size_t)(row0 + rr) * Wd + j), R);
    }
}

extern "C" void kernel_launch(void* const* d_in, const int* in_sizes, int n_in,
                              void* d_out, int out_size) {
    const float* img = (const float*)d_in[0];
    float* out = (float*)d_out;
    const int smem = H_IN * IN_STRIDE * sizeof(float);   // 49536 B
    cudaFuncSetAttribute(stencil4_kernel,
                         cudaFuncAttributeMaxDynamicSharedMemorySize, smem);
    dim3 grid(Hd / H_TILE, Nd);   // 128 x 32 = 4096 CTAs
    dim3 block(256);
    stencil4_kernel<<<grid, block, smem>>>(img, out);
}